// round 11
// baseline (speedup 1.0000x reference)
#include <cuda_runtime.h>
#include <cuda_bf16.h>
#include <cstdint>

#define N_NODES 100000
#define N_EDGES 3200000
#define BATCH   16
#define HIDDEN  64

// Lookup table for the scalar MLP f(x): 1 -> 64 GELU(erf) -> 1
#define TBL_N     16384
#define TBL_RANGE 10.0f
#define TBL_SCALE ((float)TBL_N / (2.0f * TBL_RANGE))
#define TBL_OFF   ((float)TBL_N * 0.5f)

#define TBL_BLOCKS  ((TBL_N + 1 + 255) / 256)            // 65
#define PREP_BLOCKS ((N_NODES + 255) / 256)              // 391

// Degree histogram: privatized per-block byte-packed partials
#define N_WORDS     25000                                 // N_NODES / 4 nodes-per-word
#define HIST_PARTS  64                                    // blocks = partial histograms
#define PART_STRIDE 25002                                 // padded even for uint2 loads
#define HIST_SMEM   (N_WORDS * 4)                         // 100000 B dynamic smem

// Scratch (device globals; zero-initialized at module load).
// INVARIANT: g_agg is all-zero at kernel_launch entry — loader zero-init on
// first call; mlp_kernel consume-and-reset afterwards. g_part is fully
// overwritten by hist_kernel every call (no reset needed).
__device__ __align__(16) float    g_muT[(size_t)N_NODES * BATCH];  // mu transposed [N][B]
__device__ __align__(16) float    g_agg[(size_t)N_NODES * BATCH];  // accumulators  [N][B]
__device__ __align__(16) unsigned g_part[(size_t)HIST_PARTS * PART_STRIDE + 16];
__device__ float                  g_tbl[TBL_N + 2];                // f(x) samples

// ---------------------------------------------------------------------------
// Exact scalar MLP (erf GELU) — table build + rare out-of-range fallback.
// ---------------------------------------------------------------------------
__device__ __forceinline__ float mlp_exact(float x,
                                           const float* __restrict__ W1,
                                           const float* __restrict__ b1,
                                           const float* __restrict__ W2,
                                           const float* __restrict__ b2) {
    float acc = b2[0];
    #pragma unroll 8
    for (int h = 0; h < HIDDEN; h++) {
        const float z = fmaf(x, __ldg(W1 + h), __ldg(b1 + h));
        const float g = 0.5f * z * (1.0f + erff(z * 0.70710678118654752440f));
        acc = fmaf(g, __ldg(W2 + h), acc);
    }
    return acc;
}

__device__ __forceinline__ float lut_eval(float x,
                                          const float* __restrict__ W1,
                                          const float* __restrict__ b1,
                                          const float* __restrict__ W2,
                                          const float* __restrict__ b2) {
    const float u = fmaf(x, TBL_SCALE, TBL_OFF);
    if (u >= 0.0f && u < (float)TBL_N) {
        const int   i    = (int)u;
        const float frac = u - (float)i;
        const float t0 = __ldg(g_tbl + i);
        const float t1 = __ldg(g_tbl + i + 1);
        return fmaf(t1 - t0, frac, t0);
    }
    return mlp_exact(x, W1, b1, W2, b2);   // |x| > 10: essentially never
}

// ---------------------------------------------------------------------------
// Kernel 0: privatized degree histogram. Each of HIST_PARTS blocks builds a
// full byte-packed node histogram in SHARED memory (spread-address smem
// atomics — no LTS same-address serialization), then writes its partial with
// plain coalesced stores. Per-block per-node count ~Poisson(0.5) << 255.
// ---------------------------------------------------------------------------
__global__ void __launch_bounds__(1024) hist_kernel(const int* __restrict__ ei) {
    extern __shared__ unsigned sh[];
    for (int w = threadIdx.x; w < N_WORDS; w += 1024) sh[w] = 0u;
    __syncthreads();

    const int total = N_EDGES / 4;   // 800000 int4s of row 0
    for (int i = blockIdx.x * 1024 + threadIdx.x; i < total; i += HIST_PARTS * 1024) {
        const int4 rr = __ldg(reinterpret_cast<const int4*>(ei) + i);
        #pragma unroll
        for (int k = 0; k < 4; k++) {
            const int r = (k == 0) ? rr.x : (k == 1) ? rr.y : (k == 2) ? rr.z : rr.w;
            if ((unsigned)r < N_NODES)
                atomicAdd(&sh[r >> 2], 1u << ((r & 3) * 8));
        }
    }
    __syncthreads();

    unsigned* dst = g_part + (size_t)blockIdx.x * PART_STRIDE;
    for (int w = threadIdx.x; w < N_WORDS; w += 1024) dst[w] = sh[w];
}

// ---------------------------------------------------------------------------
// Kernel 1 (merged, 2 block ranges): LUT build + mu transpose (R6 form).
// ---------------------------------------------------------------------------
__global__ void __launch_bounds__(256) init_kernel(const float* __restrict__ mu,
                                                   const float* __restrict__ W1,
                                                   const float* __restrict__ b1,
                                                   const float* __restrict__ W2,
                                                   const float* __restrict__ b2) {
    if (blockIdx.x < TBL_BLOCKS) {
        const int i = blockIdx.x * 256 + threadIdx.x;
        if (i <= TBL_N) {
            const float x = -TBL_RANGE + (2.0f * TBL_RANGE / (float)TBL_N) * (float)i;
            g_tbl[i] = mlp_exact(x, W1, b1, W2, b2);
        }
        return;
    }

    const int n = (blockIdx.x - TBL_BLOCKS) * 256 + threadIdx.x;
    if (n >= N_NODES) return;

    float v[BATCH];
    #pragma unroll
    for (int b = 0; b < BATCH; b++)
        v[b] = __ldg(mu + (size_t)b * N_NODES + n);

    float4* dst = reinterpret_cast<float4*>(g_muT) + (size_t)n * 4;
    dst[0] = make_float4(v[0],  v[1],  v[2],  v[3]);
    dst[1] = make_float4(v[4],  v[5],  v[6],  v[7]);
    dst[2] = make_float4(v[8],  v[9],  v[10], v[11]);
    dst[3] = make_float4(v[12], v[13], v[14], v[15]);
}

// ---------------------------------------------------------------------------
// Kernel 2: per-edge scatter, 4 lanes per edge (8 edges per warp).
// Pure gather + v4-RED (measured-best form: ~43us).
// ---------------------------------------------------------------------------
__device__ __forceinline__ void red_add_v4(float* gptr, float4 v) {
    asm volatile("red.global.add.v4.f32 [%0], {%1, %2, %3, %4};"
                 :: "l"(__cvta_generic_to_global(gptr)),
                    "f"(v.x), "f"(v.y), "f"(v.z), "f"(v.w)
                 : "memory");
}

__global__ void __launch_bounds__(256) edge_kernel(const int* __restrict__ ei) {
    const int T = blockIdx.x * blockDim.x + threadIdx.x;
    const int e = T >> 2;        // edge id
    const int q = T & 3;         // float4 slot within the 64B row
    if (e >= N_EDGES) return;

    const int r = __ldg(ei + e);             // destination (row)
    const int c = __ldg(ei + N_EDGES + e);   // source (col)
    if ((unsigned)r >= N_NODES || (unsigned)c >= N_NODES) return;

    const float4 v = reinterpret_cast<const float4*>(g_muT)[(size_t)c * 4 + q];
    red_add_v4(g_agg + (size_t)r * BATCH + q * 4, v);
}

// ---------------------------------------------------------------------------
// Kernel 3: merge degree partials (per-warp shfl reduction) + mean + LUT MLP,
// then CONSUME-AND-RESET of g_agg for the next graph replay.
// Each warp covers 8 nodes = 2 adjacent histogram words; lanes load uint2
// across the 64 partials (2 loads/lane) and byte-wise shfl-reduce (per-byte
// totals = node degree <= ~70 < 256, so no carries ever cross bytes).
// ---------------------------------------------------------------------------
__global__ void __launch_bounds__(512) mlp_kernel(const float* __restrict__ W1,
                                                  const float* __restrict__ b1,
                                                  const float* __restrict__ W2,
                                                  const float* __restrict__ b2,
                                                  float* __restrict__ out) {
    __shared__ float tileY[BATCH][128 + 4];

    const int t    = threadIdx.x;
    const int n0   = blockIdx.x * 128;
    const int node = t >> 2;
    const int q    = t & 3;
    const int n    = n0 + node;

    // --- degree merge: warp covers nodes [nw0, nw0+8) = words wb, wb+1 ---
    const int lane = t & 31;
    const int nw0  = n0 + ((t >> 5) << 3);       // first node of this warp
    unsigned degw0 = 0, degw1 = 0;
    if (nw0 < N_NODES) {                          // warp-uniform condition
        const int wb = nw0 >> 2;                  // even (nw0 % 8 == 0)
        uint2 s = make_uint2(0u, 0u);
        #pragma unroll
        for (int k = 0; k < HIST_PARTS / 32; k++) {
            const int p = lane + k * 32;
            const uint2 v = *reinterpret_cast<const uint2*>(
                g_part + (size_t)p * PART_STRIDE + wb);
            s.x += v.x; s.y += v.y;               // byte-wise safe (no carry)
        }
        #pragma unroll
        for (int off = 16; off; off >>= 1) {
            s.x += __shfl_xor_sync(0xFFFFFFFFu, s.x, off);
            s.y += __shfl_xor_sync(0xFFFFFFFFu, s.y, off);
        }
        degw0 = s.x; degw1 = s.y;
    }

    float4 y = make_float4(0.f, 0.f, 0.f, 0.f);
    if (n < N_NODES) {
        const unsigned dw  = ((node & 7) < 4) ? degw0 : degw1;
        const unsigned deg = (dw >> ((n & 3) * 8)) & 0xFFu;
        const float invd = 1.0f / (float)(deg ? deg : 1u);
        float4* aggp = reinterpret_cast<float4*>(g_agg) + (size_t)n * 4 + q;
        const float4 a = *aggp;
        *aggp = make_float4(0.f, 0.f, 0.f, 0.f);    // reset for next replay
        y.x = lut_eval(a.x * invd, W1, b1, W2, b2);
        y.y = lut_eval(a.y * invd, W1, b1, W2, b2);
        y.z = lut_eval(a.z * invd, W1, b1, W2, b2);
        y.w = lut_eval(a.w * invd, W1, b1, W2, b2);
    }
    tileY[q * 4 + 0][node] = y.x;
    tileY[q * 4 + 1][node] = y.y;
    tileY[q * 4 + 2][node] = y.z;
    tileY[q * 4 + 3][node] = y.w;
    __syncthreads();

    const int j = t & 127;
    #pragma unroll
    for (int r = 0; r < 4; r++) {
        const int b  = (t >> 7) + r * 4;
        const int nn = n0 + j;
        if (nn < N_NODES) out[(size_t)b * N_NODES + nn] = tileY[b][j];
    }
}

// ---------------------------------------------------------------------------
extern "C" void kernel_launch(void* const* d_in, const int* in_sizes, int n_in,
                              void* d_out, int out_size) {
    const float* mu = (const float*)d_in[0];
    const int*   ei = (const int*)d_in[1];     // edge_index stored as int32
    const float* W1 = (const float*)d_in[2];
    const float* b1 = (const float*)d_in[3];
    const float* W2 = (const float*)d_in[4];
    const float* b2 = (const float*)d_in[5];
    float*      out = (float*)d_out;

    static bool attr_done = false;             // host-side, idempotent config
    if (!attr_done) {
        cudaFuncSetAttribute(hist_kernel,
                             cudaFuncAttributeMaxDynamicSharedMemorySize, HIST_SMEM);
        attr_done = true;
    }

    hist_kernel<<<HIST_PARTS, 1024, HIST_SMEM>>>(ei);
    init_kernel<<<TBL_BLOCKS + PREP_BLOCKS, 256>>>(mu, W1, b1, W2, b2);

    const long long lanes = (long long)N_EDGES * 4;
    edge_kernel<<<(int)((lanes + 255) / 256), 256>>>(ei);

    mlp_kernel<<<(N_NODES + 127) / 128, 512>>>(W1, b1, W2, b2, out);
}

// round 13
// speedup vs baseline: 1.3796x; 1.3796x over previous
#include <cuda_runtime.h>
#include <cuda_fp16.h>
#include <cstdint>

#define N_NODES 100000
#define N_EDGES 3200000
#define BATCH   16
#define HIDDEN  64
#define NBANK   8                      // accumulation banks (error + contention ÷8)

// Lookup table for the scalar MLP f(x): 1 -> 64 GELU(erf) -> 1
#define TBL_N     16384
#define TBL_RANGE 10.0f
#define TBL_SCALE ((float)TBL_N / (2.0f * TBL_RANGE))
#define TBL_OFF   ((float)TBL_N * 0.5f)

#define TBL_BLOCKS  ((TBL_N + 1 + 255) / 256)            // 65
#define PREP_BLOCKS ((N_NODES + 255) / 256)              // 391

// Scratch (device globals; zero-initialized at module load).
// INVARIANT: g_agg16 (all banks) and g_deg are all-zero at kernel_launch
// entry — loader zero-init on first call; mlp_kernel consume-and-reset after.
// g_agg16 layout is BANK-major: [bank][node][16 halves] so the mlp merge
// reads each bank as a fully-coalesced stream.
__device__ __align__(16) unsigned g_muT16[(size_t)N_NODES * 8];          // mu fp16 [N][16]
__device__ __align__(16) unsigned g_agg16[(size_t)NBANK * N_NODES * 8];  // fp16 acc banks
__device__ float                  g_deg[N_NODES];                        // exact f32 degrees
__device__ float                  g_tbl[TBL_N + 2];                      // f(x) samples

// ---------------------------------------------------------------------------
// Exact scalar MLP (erf GELU) — table build + rare out-of-range fallback.
// ---------------------------------------------------------------------------
__device__ __forceinline__ float mlp_exact(float x,
                                           const float* __restrict__ W1,
                                           const float* __restrict__ b1,
                                           const float* __restrict__ W2,
                                           const float* __restrict__ b2) {
    float acc = b2[0];
    #pragma unroll 8
    for (int h = 0; h < HIDDEN; h++) {
        const float z = fmaf(x, __ldg(W1 + h), __ldg(b1 + h));
        const float g = 0.5f * z * (1.0f + erff(z * 0.70710678118654752440f));
        acc = fmaf(g, __ldg(W2 + h), acc);
    }
    return acc;
}

__device__ __forceinline__ float lut_eval(float x,
                                          const float* __restrict__ W1,
                                          const float* __restrict__ b1,
                                          const float* __restrict__ W2,
                                          const float* __restrict__ b2) {
    const float u = fmaf(x, TBL_SCALE, TBL_OFF);
    if (u >= 0.0f && u < (float)TBL_N) {
        const int   i    = (int)u;
        const float frac = u - (float)i;
        const float t0 = __ldg(g_tbl + i);
        const float t1 = __ldg(g_tbl + i + 1);
        return fmaf(t1 - t0, frac, t0);
    }
    return mlp_exact(x, W1, b1, W2, b2);   // |x| > 10: essentially never
}

// ---------------------------------------------------------------------------
// Kernel 1 (merged, 2 block ranges): LUT build + mu transpose to fp16.
// ---------------------------------------------------------------------------
__global__ void __launch_bounds__(256) init_kernel(const float* __restrict__ mu,
                                                   const float* __restrict__ W1,
                                                   const float* __restrict__ b1,
                                                   const float* __restrict__ W2,
                                                   const float* __restrict__ b2) {
    if (blockIdx.x < TBL_BLOCKS) {
        const int i = blockIdx.x * 256 + threadIdx.x;
        if (i <= TBL_N) {
            const float x = -TBL_RANGE + (2.0f * TBL_RANGE / (float)TBL_N) * (float)i;
            g_tbl[i] = mlp_exact(x, W1, b1, W2, b2);
        }
        return;
    }

    const int n = (blockIdx.x - TBL_BLOCKS) * 256 + threadIdx.x;
    if (n >= N_NODES) return;

    float v[BATCH];
    #pragma unroll
    for (int b = 0; b < BATCH; b++)
        v[b] = __ldg(mu + (size_t)b * N_NODES + n);

    unsigned h[8];
    #pragma unroll
    for (int k = 0; k < 8; k++) {
        const __half2 p = __float22half2_rn(make_float2(v[2 * k], v[2 * k + 1]));
        h[k] = *reinterpret_cast<const unsigned*>(&p);
    }
    uint4* dst = reinterpret_cast<uint4*>(g_muT16 + (size_t)n * 8);
    dst[0] = make_uint4(h[0], h[1], h[2], h[3]);
    dst[1] = make_uint4(h[4], h[5], h[6], h[7]);
}

// ---------------------------------------------------------------------------
// Kernel 2: per-edge scatter, 2 lanes per edge (16 edges per warp).
// Each lane moves 16B (8 fp16 batches) with ONE red.global.add.noftz.v4.f16x2
// into bank (e & 7): 6.4M vector REDs + 3.2M exact f32 deg REDs.
// Banking splits each node's accumulation into ~deg/8-long chains, cutting
// fp16 accumulation error ~sqrt(8) and same-address RED concurrency 8x.
// ---------------------------------------------------------------------------
__global__ void __launch_bounds__(256) edge_kernel(const int* __restrict__ ei) {
    const int T = blockIdx.x * blockDim.x + threadIdx.x;
    const int e = T >> 1;        // edge id
    const int q = T & 1;         // which 16B half of the 32B row
    if (e >= N_EDGES) return;

    const int r = __ldg(ei + e);             // destination (row)
    const int c = __ldg(ei + N_EDGES + e);   // source (col)
    if ((unsigned)r >= N_NODES || (unsigned)c >= N_NODES) return;

    const uint4 v = *reinterpret_cast<const uint4*>(g_muT16 + (size_t)c * 8 + q * 4);
    unsigned* dst = g_agg16 + ((size_t)(e & (NBANK - 1)) * N_NODES + r) * 8 + q * 4;
    asm volatile("red.global.add.noftz.v4.f16x2 [%0], {%1, %2, %3, %4};"
                 :: "l"(__cvta_generic_to_global(dst)),
                    "r"(v.x), "r"(v.y), "r"(v.z), "r"(v.w)
                 : "memory");

    if (q == 0) {
        asm volatile("red.global.add.f32 [%0], %1;"
                     :: "l"(__cvta_generic_to_global(g_deg + r)), "f"(1.0f)
                     : "memory");
    }
}

// ---------------------------------------------------------------------------
// Kernel 3: merge the 8 fp16 banks in f32, mean, LUT MLP, staged coalesced
// write-out. CONSUME-AND-RESET of g_agg16 (all banks) and g_deg for the
// next graph replay. One thread = 8 batches (one 16B half) of one node;
// bank-major layout makes each bank's read/reset a coalesced stream.
// ---------------------------------------------------------------------------
__global__ void __launch_bounds__(512) mlp_kernel(const float* __restrict__ W1,
                                                  const float* __restrict__ b1,
                                                  const float* __restrict__ W2,
                                                  const float* __restrict__ b2,
                                                  float* __restrict__ out) {
    __shared__ float tileY[BATCH][256 + 4];

    const int t    = threadIdx.x;
    const int n0   = blockIdx.x * 256;
    const int node = t >> 1;
    const int q    = t & 1;
    const int n    = n0 + node;

    float dg = 0.0f;
    if (n < N_NODES) dg = g_deg[n];
    __syncwarp();                                   // both q-lanes read before reset
    if (n < N_NODES && q == 0) g_deg[n] = 0.0f;     // reset for next replay

    float y[8];
    #pragma unroll
    for (int k = 0; k < 8; k++) y[k] = 0.0f;

    if (n < N_NODES) {
        float s[8];
        #pragma unroll
        for (int k = 0; k < 8; k++) s[k] = 0.0f;

        #pragma unroll
        for (int bk = 0; bk < NBANK; bk++) {
            uint4* ap = reinterpret_cast<uint4*>(
                g_agg16 + ((size_t)bk * N_NODES + n) * 8 + q * 4);
            const uint4 a = *ap;
            *ap = make_uint4(0u, 0u, 0u, 0u);       // reset for next replay
            unsigned w[4] = {a.x, a.y, a.z, a.w};
            #pragma unroll
            for (int k = 0; k < 4; k++) {
                const float2 f = __half22float2(*reinterpret_cast<const __half2*>(&w[k]));
                s[2 * k + 0] += f.x;
                s[2 * k + 1] += f.y;
            }
        }

        const float invd = 1.0f / fmaxf(dg, 1.0f);
        #pragma unroll
        for (int k = 0; k < 8; k++)
            y[k] = lut_eval(s[k] * invd, W1, b1, W2, b2);
    }
    #pragma unroll
    for (int k = 0; k < 8; k++)
        tileY[q * 8 + k][node] = y[k];
    __syncthreads();

    const int j  = t & 255;
    const int b0 = t >> 8;                          // 0..1
    #pragma unroll
    for (int r = 0; r < 8; r++) {
        const int b  = b0 * 8 + r;
        const int nn = n0 + j;
        if (nn < N_NODES) out[(size_t)b * N_NODES + nn] = tileY[b][j];
    }
}

// ---------------------------------------------------------------------------
extern "C" void kernel_launch(void* const* d_in, const int* in_sizes, int n_in,
                              void* d_out, int out_size) {
    const float* mu = (const float*)d_in[0];
    const int*   ei = (const int*)d_in[1];     // edge_index stored as int32
    const float* W1 = (const float*)d_in[2];
    const float* b1 = (const float*)d_in[3];
    const float* W2 = (const float*)d_in[4];
    const float* b2 = (const float*)d_in[5];
    float*      out = (float*)d_out;

    init_kernel<<<TBL_BLOCKS + PREP_BLOCKS, 256>>>(mu, W1, b1, W2, b2);

    const long long lanes = (long long)N_EDGES * 2;
    edge_kernel<<<(int)((lanes + 255) / 256), 256>>>(ei);

    mlp_kernel<<<(N_NODES + 255) / 256, 512>>>(W1, b1, W2, b2, out);
}

// round 14
// speedup vs baseline: 1.4311x; 1.0374x over previous
#include <cuda_runtime.h>
#include <cuda_fp16.h>
#include <cstdint>

#define N_NODES 100000
#define N_EDGES 3200000
#define BATCH   16
#define HIDDEN  64
#define NBANK   4                      // accumulation banks (calibrated err ~6.3e-4)

// Lookup table for the scalar MLP f(x): 1 -> 64 GELU(erf) -> 1
#define TBL_N     16384
#define TBL_RANGE 10.0f
#define TBL_SCALE ((float)TBL_N / (2.0f * TBL_RANGE))
#define TBL_OFF   ((float)TBL_N * 0.5f)

#define TBL_BLOCKS  ((TBL_N + 1 + 255) / 256)            // 65
#define PREP_BLOCKS ((N_NODES * 4 + 255) / 256)          // 1563 (4 threads/node)

// Scratch (device globals; zero-initialized at module load).
// INVARIANT: g_agg16 (all banks) and g_deg are all-zero at kernel_launch
// entry — loader zero-init on first call; mlp_kernel consume-and-reset after.
// g_agg16 is BANK-major: [bank][node][16 halves] -> coalesced merge streams.
__device__ __align__(16) unsigned g_muT16[(size_t)N_NODES * 8];          // mu fp16 [N][16]
__device__ __align__(16) unsigned g_agg16[(size_t)NBANK * N_NODES * 8];  // fp16 acc banks
__device__ float                  g_deg[N_NODES];                        // exact f32 degrees
__device__ float                  g_tbl[TBL_N + 2];                      // f(x) samples

// ---------------------------------------------------------------------------
// Exact scalar MLP (erf GELU) — table build + rare out-of-range fallback.
// ---------------------------------------------------------------------------
__device__ __forceinline__ float mlp_exact(float x,
                                           const float* __restrict__ W1,
                                           const float* __restrict__ b1,
                                           const float* __restrict__ W2,
                                           const float* __restrict__ b2) {
    float acc = b2[0];
    #pragma unroll 8
    for (int h = 0; h < HIDDEN; h++) {
        const float z = fmaf(x, __ldg(W1 + h), __ldg(b1 + h));
        const float g = 0.5f * z * (1.0f + erff(z * 0.70710678118654752440f));
        acc = fmaf(g, __ldg(W2 + h), acc);
    }
    return acc;
}

__device__ __forceinline__ float lut_eval(float x,
                                          const float* __restrict__ W1,
                                          const float* __restrict__ b1,
                                          const float* __restrict__ W2,
                                          const float* __restrict__ b2) {
    const float u = fmaf(x, TBL_SCALE, TBL_OFF);
    if (u >= 0.0f && u < (float)TBL_N) {
        const int   i    = (int)u;
        const float frac = u - (float)i;
        const float t0 = __ldg(g_tbl + i);
        const float t1 = __ldg(g_tbl + i + 1);
        return fmaf(t1 - t0, frac, t0);
    }
    return mlp_exact(x, W1, b1, W2, b2);   // |x| > 10: essentially never
}

// ---------------------------------------------------------------------------
// Kernel 1 (merged, 2 block ranges): LUT build + mu transpose to fp16.
// Transpose uses 4 threads per node (4 strided LDGs + one 8B store each):
// 4x the parallelism of the 1-thread/node form, which was latency-bound
// at occ 27%.
// ---------------------------------------------------------------------------
__global__ void __launch_bounds__(256) init_kernel(const float* __restrict__ mu,
                                                   const float* __restrict__ W1,
                                                   const float* __restrict__ b1,
                                                   const float* __restrict__ W2,
                                                   const float* __restrict__ b2) {
    if (blockIdx.x < TBL_BLOCKS) {
        const int i = blockIdx.x * 256 + threadIdx.x;
        if (i <= TBL_N) {
            const float x = -TBL_RANGE + (2.0f * TBL_RANGE / (float)TBL_N) * (float)i;
            g_tbl[i] = mlp_exact(x, W1, b1, W2, b2);
        }
        return;
    }

    const int idx  = (blockIdx.x - TBL_BLOCKS) * 256 + threadIdx.x;
    const int n    = idx >> 2;          // node
    const int part = idx & 3;           // which 4-batch slice
    if (n >= N_NODES) return;

    const int b0 = part * 4;
    float v0 = __ldg(mu + (size_t)(b0 + 0) * N_NODES + n);
    float v1 = __ldg(mu + (size_t)(b0 + 1) * N_NODES + n);
    float v2 = __ldg(mu + (size_t)(b0 + 2) * N_NODES + n);
    float v3 = __ldg(mu + (size_t)(b0 + 3) * N_NODES + n);

    const __half2 p0 = __float22half2_rn(make_float2(v0, v1));
    const __half2 p1 = __float22half2_rn(make_float2(v2, v3));
    uint2 w;
    w.x = *reinterpret_cast<const unsigned*>(&p0);
    w.y = *reinterpret_cast<const unsigned*>(&p1);
    *reinterpret_cast<uint2*>(g_muT16 + (size_t)n * 8 + part * 2) = w;
}

// ---------------------------------------------------------------------------
// Kernel 2: per-edge scatter, 2 lanes per edge (16 edges per warp).
// Each lane moves 16B (8 fp16 batches) with ONE red.global.add.noftz.v4.f16x2
// into bank (e & 3): 6.4M vector REDs + 3.2M exact f32 deg REDs.
// ---------------------------------------------------------------------------
__global__ void __launch_bounds__(256) edge_kernel(const int* __restrict__ ei) {
    const int T = blockIdx.x * blockDim.x + threadIdx.x;
    const int e = T >> 1;        // edge id
    const int q = T & 1;         // which 16B half of the 32B row
    if (e >= N_EDGES) return;

    const int r = __ldg(ei + e);             // destination (row)
    const int c = __ldg(ei + N_EDGES + e);   // source (col)
    if ((unsigned)r >= N_NODES || (unsigned)c >= N_NODES) return;

    const uint4 v = *reinterpret_cast<const uint4*>(g_muT16 + (size_t)c * 8 + q * 4);
    unsigned* dst = g_agg16 + ((size_t)(e & (NBANK - 1)) * N_NODES + r) * 8 + q * 4;
    asm volatile("red.global.add.noftz.v4.f16x2 [%0], {%1, %2, %3, %4};"
                 :: "l"(__cvta_generic_to_global(dst)),
                    "r"(v.x), "r"(v.y), "r"(v.z), "r"(v.w)
                 : "memory");

    if (q == 0) {
        asm volatile("red.global.add.f32 [%0], %1;"
                     :: "l"(__cvta_generic_to_global(g_deg + r)), "f"(1.0f)
                     : "memory");
    }
}

// ---------------------------------------------------------------------------
// Kernel 3: merge the 4 fp16 banks in f32, mean, LUT MLP, staged coalesced
// write-out. CONSUME-AND-RESET of g_agg16 (all banks) and g_deg for the
// next graph replay.
// ---------------------------------------------------------------------------
__global__ void __launch_bounds__(512) mlp_kernel(const float* __restrict__ W1,
                                                  const float* __restrict__ b1,
                                                  const float* __restrict__ W2,
                                                  const float* __restrict__ b2,
                                                  float* __restrict__ out) {
    __shared__ float tileY[BATCH][256 + 4];

    const int t    = threadIdx.x;
    const int n0   = blockIdx.x * 256;
    const int node = t >> 1;
    const int q    = t & 1;
    const int n    = n0 + node;

    float dg = 0.0f;
    if (n < N_NODES) dg = g_deg[n];
    __syncwarp();                                   // both q-lanes read before reset
    if (n < N_NODES && q == 0) g_deg[n] = 0.0f;     // reset for next replay

    float y[8];
    #pragma unroll
    for (int k = 0; k < 8; k++) y[k] = 0.0f;

    if (n < N_NODES) {
        float s[8];
        #pragma unroll
        for (int k = 0; k < 8; k++) s[k] = 0.0f;

        #pragma unroll
        for (int bk = 0; bk < NBANK; bk++) {
            uint4* ap = reinterpret_cast<uint4*>(
                g_agg16 + ((size_t)bk * N_NODES + n) * 8 + q * 4);
            const uint4 a = *ap;
            *ap = make_uint4(0u, 0u, 0u, 0u);       // reset for next replay
            unsigned w[4] = {a.x, a.y, a.z, a.w};
            #pragma unroll
            for (int k = 0; k < 4; k++) {
                const float2 f = __half22float2(*reinterpret_cast<const __half2*>(&w[k]));
                s[2 * k + 0] += f.x;
                s[2 * k + 1] += f.y;
            }
        }

        const float invd = 1.0f / fmaxf(dg, 1.0f);
        #pragma unroll
        for (int k = 0; k < 8; k++)
            y[k] = lut_eval(s[k] * invd, W1, b1, W2, b2);
    }
    #pragma unroll
    for (int k = 0; k < 8; k++)
        tileY[q * 8 + k][node] = y[k];
    __syncthreads();

    const int j  = t & 255;
    const int b0 = t >> 8;                          // 0..1
    #pragma unroll
    for (int r = 0; r < 8; r++) {
        const int b  = b0 * 8 + r;
        const int nn = n0 + j;
        if (nn < N_NODES) out[(size_t)b * N_NODES + nn] = tileY[b][j];
    }
}

// ---------------------------------------------------------------------------
extern "C" void kernel_launch(void* const* d_in, const int* in_sizes, int n_in,
                              void* d_out, int out_size) {
    const float* mu = (const float*)d_in[0];
    const int*   ei = (const int*)d_in[1];     // edge_index stored as int32
    const float* W1 = (const float*)d_in[2];
    const float* b1 = (const float*)d_in[3];
    const float* W2 = (const float*)d_in[4];
    const float* b2 = (const float*)d_in[5];
    float*      out = (float*)d_out;

    init_kernel<<<TBL_BLOCKS + PREP_BLOCKS, 256>>>(mu, W1, b1, W2, b2);

    const long long lanes = (long long)N_EDGES * 2;
    edge_kernel<<<(int)((lanes + 255) / 256), 256>>>(ei);

    mlp_kernel<<<(N_NODES + 255) / 256, 512>>>(W1, b1, W2, b2, out);
}

// round 16
// speedup vs baseline: 1.4595x; 1.0198x over previous
#include <cuda_runtime.h>
#include <cuda_fp16.h>
#include <cstdint>

#define N_NODES 100000
#define N_EDGES 3200000
#define BATCH   16
#define HIDDEN  64
#define NBANK   4                      // accumulation banks (calibrated err ~6.1e-4)

// Lookup table for the scalar MLP f(x): 1 -> 64 GELU(erf) -> 1
#define TBL_N     16384
#define TBL_RANGE 10.0f
#define TBL_SCALE ((float)TBL_N / (2.0f * TBL_RANGE))
#define TBL_OFF   ((float)TBL_N * 0.5f)

#define TBL_BLOCKS  ((TBL_N + 1 + 255) / 256)            // 65
#define PREP_BLOCKS ((N_NODES * 4 + 255) / 256)          // 1563 (4 threads/node)

// Scratch (device globals; zero-initialized at module load).
// INVARIANT: g_agg16 (all banks) and g_deg are all-zero at kernel_launch
// entry — loader zero-init on first call; mlp_kernel consume-and-reset after.
// g_agg16 is BANK-major: [bank][node][16 halves] -> coalesced merge streams.
__device__ __align__(16) unsigned g_muT16[(size_t)N_NODES * 8];          // mu fp16 [N][16]
__device__ __align__(16) unsigned g_agg16[(size_t)NBANK * N_NODES * 8];  // fp16 acc banks
__device__ float                  g_deg[N_NODES];                        // exact f32 degrees
__device__ float                  g_tbl[TBL_N + 2];                      // f(x) samples

// ---------------------------------------------------------------------------
// Exact scalar MLP (erf GELU) — table build + rare out-of-range fallback.
// ---------------------------------------------------------------------------
__device__ __forceinline__ float mlp_exact(float x,
                                           const float* __restrict__ W1,
                                           const float* __restrict__ b1,
                                           const float* __restrict__ W2,
                                           const float* __restrict__ b2) {
    float acc = b2[0];
    #pragma unroll 8
    for (int h = 0; h < HIDDEN; h++) {
        const float z = fmaf(x, __ldg(W1 + h), __ldg(b1 + h));
        const float g = 0.5f * z * (1.0f + erff(z * 0.70710678118654752440f));
        acc = fmaf(g, __ldg(W2 + h), acc);
    }
    return acc;
}

__device__ __forceinline__ float lut_eval(float x,
                                          const float* __restrict__ W1,
                                          const float* __restrict__ b1,
                                          const float* __restrict__ W2,
                                          const float* __restrict__ b2) {
    const float u = fmaf(x, TBL_SCALE, TBL_OFF);
    if (u >= 0.0f && u < (float)TBL_N) {
        const int   i    = (int)u;
        const float frac = u - (float)i;
        const float t0 = __ldg(g_tbl + i);
        const float t1 = __ldg(g_tbl + i + 1);
        return fmaf(t1 - t0, frac, t0);
    }
    return mlp_exact(x, W1, b1, W2, b2);   // |x| > 10: essentially never
}

// ---------------------------------------------------------------------------
// Kernel 1 (merged, 2 block ranges): LUT build + mu transpose to fp16.
// Transpose: 4 threads per node (4 strided LDGs + one 8B store each).
// ---------------------------------------------------------------------------
__global__ void __launch_bounds__(256) init_kernel(const float* __restrict__ mu,
                                                   const float* __restrict__ W1,
                                                   const float* __restrict__ b1,
                                                   const float* __restrict__ W2,
                                                   const float* __restrict__ b2) {
    if (blockIdx.x < TBL_BLOCKS) {
        const int i = blockIdx.x * 256 + threadIdx.x;
        if (i <= TBL_N) {
            const float x = -TBL_RANGE + (2.0f * TBL_RANGE / (float)TBL_N) * (float)i;
            g_tbl[i] = mlp_exact(x, W1, b1, W2, b2);
        }
        return;
    }

    const int idx  = (blockIdx.x - TBL_BLOCKS) * 256 + threadIdx.x;
    const int n    = idx >> 2;          // node
    const int part = idx & 3;           // which 4-batch slice
    if (n >= N_NODES) return;

    const int b0 = part * 4;
    float v0 = __ldg(mu + (size_t)(b0 + 0) * N_NODES + n);
    float v1 = __ldg(mu + (size_t)(b0 + 1) * N_NODES + n);
    float v2 = __ldg(mu + (size_t)(b0 + 2) * N_NODES + n);
    float v3 = __ldg(mu + (size_t)(b0 + 3) * N_NODES + n);

    const __half2 p0 = __float22half2_rn(make_float2(v0, v1));
    const __half2 p1 = __float22half2_rn(make_float2(v2, v3));
    uint2 w;
    w.x = *reinterpret_cast<const unsigned*>(&p0);
    w.y = *reinterpret_cast<const unsigned*>(&p1);
    *reinterpret_cast<uint2*>(g_muT16 + (size_t)n * 8 + part * 2) = w;
}

// ---------------------------------------------------------------------------
// Kernel 2: per-edge scatter, 2 lanes per edge (16 edges per warp).
// Each lane moves 16B (8 fp16 batches) with ONE red.global.add.noftz.v4.f16x2
// into bank (e & 3): 6.4M vector REDs + 3.2M exact f32 deg REDs = 9.6M LTS
// ops — the structural floor given the 128-bit red vector cap.
// ---------------------------------------------------------------------------
__global__ void __launch_bounds__(256) edge_kernel(const int* __restrict__ ei) {
    const int T = blockIdx.x * blockDim.x + threadIdx.x;
    const int e = T >> 1;        // edge id
    const int q = T & 1;         // which 16B half of the 32B row
    if (e >= N_EDGES) return;

    const int r = __ldg(ei + e);             // destination (row)
    const int c = __ldg(ei + N_EDGES + e);   // source (col)
    if ((unsigned)r >= N_NODES || (unsigned)c >= N_NODES) return;

    const uint4 v = *reinterpret_cast<const uint4*>(g_muT16 + (size_t)c * 8 + q * 4);
    unsigned* dst = g_agg16 + ((size_t)(e & (NBANK - 1)) * N_NODES + r) * 8 + q * 4;
    asm volatile("red.global.add.noftz.v4.f16x2 [%0], {%1, %2, %3, %4};"
                 :: "l"(__cvta_generic_to_global(dst)),
                    "r"(v.x), "r"(v.y), "r"(v.z), "r"(v.w)
                 : "memory");

    if (q == 0) {
        asm volatile("red.global.add.f32 [%0], %1;"
                     :: "l"(__cvta_generic_to_global(g_deg + r)), "f"(1.0f)
                     : "memory");
    }
}

// ---------------------------------------------------------------------------
// Kernel 3: merge the 4 fp16 banks in f32, mean, LUT MLP, staged coalesced
// write-out. ONE THREAD = ONE NODE: 8 independent uint4 loads in flight
// (4 banks x 2), thread-private deg read+reset (no warp handshake), 16 LUT
// evals. CONSUME-AND-RESET of g_agg16 and g_deg for the next graph replay.
// ---------------------------------------------------------------------------
__global__ void __launch_bounds__(256) mlp_kernel(const float* __restrict__ W1,
                                                  const float* __restrict__ b1,
                                                  const float* __restrict__ W2,
                                                  const float* __restrict__ b2,
                                                  float* __restrict__ out) {
    __shared__ float tileY[BATCH][256 + 4];

    const int t  = threadIdx.x;
    const int n0 = blockIdx.x * 256;
    const int n  = n0 + t;

    float y[BATCH];
    #pragma unroll
    for (int k = 0; k < BATCH; k++) y[k] = 0.0f;

    if (n < N_NODES) {
        const float dg = g_deg[n];
        g_deg[n] = 0.0f;                           // thread-private reset

        // 8 independent 16B loads (4 banks x 2 halves) — deep MLP
        uint4 a[NBANK][2];
        #pragma unroll
        for (int bk = 0; bk < NBANK; bk++) {
            uint4* ap = reinterpret_cast<uint4*>(
                g_agg16 + ((size_t)bk * N_NODES + n) * 8);
            a[bk][0] = ap[0];
            a[bk][1] = ap[1];
        }
        const uint4 z4 = make_uint4(0u, 0u, 0u, 0u);
        #pragma unroll
        for (int bk = 0; bk < NBANK; bk++) {
            uint4* ap = reinterpret_cast<uint4*>(
                g_agg16 + ((size_t)bk * N_NODES + n) * 8);
            ap[0] = z4;                            // reset for next replay
            ap[1] = z4;
        }

        float s[BATCH];
        #pragma unroll
        for (int k = 0; k < BATCH; k++) s[k] = 0.0f;
        #pragma unroll
        for (int bk = 0; bk < NBANK; bk++) {
            #pragma unroll
            for (int h = 0; h < 2; h++) {
                unsigned w[4] = {a[bk][h].x, a[bk][h].y, a[bk][h].z, a[bk][h].w};
                #pragma unroll
                for (int k = 0; k < 4; k++) {
                    const float2 f =
                        __half22float2(*reinterpret_cast<const __half2*>(&w[k]));
                    s[h * 8 + 2 * k + 0] += f.x;
                    s[h * 8 + 2 * k + 1] += f.y;
                }
            }
        }

        const float invd = 1.0f / fmaxf(dg, 1.0f);
        #pragma unroll
        for (int k = 0; k < BATCH; k++)
            y[k] = lut_eval(s[k] * invd, W1, b1, W2, b2);
    }

    #pragma unroll
    for (int k = 0; k < BATCH; k++)
        tileY[k][t] = y[k];
    __syncthreads();

    // coalesced write-out: 16 rows of 256 consecutive nodes
    #pragma unroll
    for (int b = 0; b < BATCH; b++) {
        const int nn = n0 + t;
        if (nn < N_NODES) out[(size_t)b * N_NODES + nn] = tileY[b][t];
    }
}

// ---------------------------------------------------------------------------
extern "C" void kernel_launch(void* const* d_in, const int* in_sizes, int n_in,
                              void* d_out, int out_size) {
    const float* mu = (const float*)d_in[0];
    const int*   ei = (const int*)d_in[1];     // edge_index stored as int32
    const float* W1 = (const float*)d_in[2];
    const float* b1 = (const float*)d_in[3];
    const float* W2 = (const float*)d_in[4];
    const float* b2 = (const float*)d_in[5];
    float*      out = (float*)d_out;

    init_kernel<<<TBL_BLOCKS + PREP_BLOCKS, 256>>>(mu, W1, b1, W2, b2);

    const long long lanes = (long long)N_EDGES * 2;
    edge_kernel<<<(int)((lanes + 255) / 256), 256>>>(ei);

    mlp_kernel<<<(N_NODES + 255) / 256, 256>>>(W1, b1, W2, b2, out);
}